// round 1
// baseline (speedup 1.0000x reference)
#include <cuda_runtime.h>
#include <math.h>

// Problem dims
#define NFREQ 211
#define NTIME 390
#define KF    422          // padded freq
#define KT    1170         // padded time
#define NFILT 119
#define FP    (NFILT*NFREQ)   // 25109 rows (f,p)
#define FPS   25216           // padded row stride (mult of 32)
#define K2    (2*KT)          // 2340 (Re rows then Im rows)
#define MT1   197             // ceil(FP/128)
#define NT2   7               // ceil(NTIME/64)

// ---------------- device scratch (static, zero-initialized) ----------------
__device__ float g_twc[KT],   g_tws[KT];
__device__ float g_t4c[KF],   g_t4s[KF];
__device__ float g_Dre[KF*NFREQ], g_Dim[KF*NFREQ];   // D[k][p] = e^{+2pi i pk/422}/422
__device__ float g_E2[K2*NTIME];                     // rows<KT: Ere ; rows>=KT: -Eim
__device__ float g_Pre[NFREQ*KT], g_Pim[NFREQ*KT];
__device__ float g_Xre[KF*KT],    g_Xim[KF*KT];
__device__ float g_V[(size_t)K2*FPS];                // rows<KT: Vre ; >=KT: Vim ; cols (f,p)
__device__ float g_Part[MT1*NT2*128];

// ---------------- twiddle / matrix builders ----------------
__global__ void k_tw() {
    int i = blockIdx.x*256 + threadIdx.x;
    if (i < KT) { double s,c; sincospi(2.0*i/KT, &s, &c); g_twc[i]=(float)c; g_tws[i]=(float)s; }
    if (i < KF) { double s,c; sincospi(2.0*i/KF, &s, &c); g_t4c[i]=(float)c; g_t4s[i]=(float)s; }
}
__global__ void k_D() {
    int i = blockIdx.x*256 + threadIdx.x;
    if (i >= KF*NFREQ) return;
    int k = i / NFREQ, p = i % NFREQ;
    int r = (k*p) % KF;
    double s,c; sincospi(2.0*r/KF, &s, &c);
    g_Dre[i] = (float)(c/KF); g_Dim[i] = (float)(s/KF);
}
__global__ void k_E2() {
    int i = blockIdx.x*256 + threadIdx.x;
    if (i >= K2*NTIME) return;
    int kap = i / NTIME, q = i % NTIME;
    int l = (kap < KT) ? kap : kap - KT;
    int r = (l*q) % KT;
    double s,c; sincospi(2.0*r/KT, &s, &c);
    g_E2[i] = (float)(((kap < KT) ? c : -s) / KT);
}

// ---------------- stage 0: X = fft2(pad(100*x)) -----------------
// P[u,l] = sum_v 100*x[u,v] * e^{-2pi i l v / KT}
__global__ void k_P(const float* __restrict__ x) {
    __shared__ float sc[KT], ss[KT];
    int tid = threadIdx.x;
    for (int i = tid; i < KT; i += 256) { sc[i]=g_twc[i]; ss[i]=g_tws[i]; }
    __syncthreads();
    int l = blockIdx.x*256 + tid;
    int u = blockIdx.y;
    if (l >= KT) return;
    const float* xr = x + u*NTIME;
    float pr = 0.f, pi = 0.f; int j = 0;
    for (int v = 0; v < NTIME; v++) {
        float xv = xr[v] * 100.0f;
        pr += xv * sc[j];
        pi -= xv * ss[j];
        j += l; if (j >= KT) j -= KT;
    }
    g_Pre[u*KT + l] = pr; g_Pim[u*KT + l] = pi;
}
// X[k,l] = sum_u P[u,l] * e^{-2pi i k u / KF}
__global__ void k_X() {
    __shared__ float sc[KF], ss[KF];
    int tid = threadIdx.x;
    for (int i = tid; i < KF; i += 256) { sc[i]=g_t4c[i]; ss[i]=g_t4s[i]; }
    __syncthreads();
    int l = blockIdx.x*256 + tid;
    int k = blockIdx.y;
    if (l >= KT) return;
    float xr = 0.f, xi = 0.f; int j = 0;
    for (int u = 0; u < NFREQ; u++) {
        float pr = g_Pre[u*KT + l], pi = g_Pim[u*KT + l];
        float c = sc[j], s = ss[j];
        xr += pr*c + pi*s;
        xi += pi*c - pr*s;
        j += k; if (j >= KF) j -= KF;
    }
    g_Xre[k*KT + l] = xr; g_Xim[k*KT + l] = xi;
}

// ---------------- stage 1: per l, V[:,l] = (H[:,:,l] o X[:,l]) * D ----------------
// CTA: fixed l, f-tile = all 128 (119 valid), p-tile of 64. Thread = 8f x 4p complex.
__global__ void __launch_bounds__(256, 2)
k_s1(const float* __restrict__ Hre, const float* __restrict__ Him) {
    int l  = blockIdx.y;
    int p0 = blockIdx.x * 64;
    int tid = threadIdx.x;
    int tx = tid & 15, ty = tid >> 4;

    __shared__ float Ar[16][128], Ai[16][128];
    __shared__ float Br[16][64],  Bi[16][64];

    float cr[8][4], ci[8][4];
    #pragma unroll
    for (int i=0;i<8;i++)
        #pragma unroll
        for (int j=0;j<4;j++) { cr[i][j]=0.f; ci[i][j]=0.f; }

    int kk_l = tid >> 4;            // loader's k within chunk
    int f0   = (tid & 15) << 3;     // loader's f base (8 consecutive)
    int pl0  = (tid & 15) << 2;     // loader's p base (4 consecutive)

    for (int kc = 0; kc < 27; kc++) {
        int kg = kc*16 + kk_l;
        float xr = 0.f, xi = 0.f;
        if (kg < KF) { xr = g_Xre[kg*KT + l]; xi = g_Xim[kg*KT + l]; }
        #pragma unroll
        for (int e = 0; e < 8; e++) {
            int f = f0 + e;
            float hr = 0.f, hi = 0.f;
            if (f < NFILT && kg < KF) {
                size_t off = ((size_t)f*KF + kg)*KT + l;
                hr = Hre[off]; hi = Him[off];
            }
            Ar[kk_l][f] = hr*xr - hi*xi;
            Ai[kk_l][f] = hr*xi + hi*xr;
        }
        #pragma unroll
        for (int e = 0; e < 4; e++) {
            int pp = pl0 + e, pg = p0 + pp;
            float dr = 0.f, di = 0.f;
            if (pg < NFREQ && kg < KF) {
                dr = g_Dre[kg*NFREQ + pg];
                di = g_Dim[kg*NFREQ + pg];
            }
            Br[kk_l][pp] = dr; Bi[kk_l][pp] = di;
        }
        __syncthreads();
        #pragma unroll
        for (int kk = 0; kk < 16; kk++) {
            float ar[8], ai2[8], br[4], bi2[4];
            #pragma unroll
            for (int i=0;i<8;i++) { ar[i]=Ar[kk][ty*8+i]; ai2[i]=Ai[kk][ty*8+i]; }
            #pragma unroll
            for (int j=0;j<4;j++) { br[j]=Br[kk][tx*4+j]; bi2[j]=Bi[kk][tx*4+j]; }
            #pragma unroll
            for (int i=0;i<8;i++) {
                float a = ar[i], b = ai2[i];
                #pragma unroll
                for (int j=0;j<4;j++) {
                    cr[i][j] += a*br[j]  - b*bi2[j];
                    ci[i][j] += a*bi2[j] + b*br[j];
                }
            }
        }
        __syncthreads();
    }
    // write V
    #pragma unroll
    for (int i=0;i<8;i++) {
        int f = ty*8 + i;
        if (f >= NFILT) break;
        #pragma unroll
        for (int j=0;j<4;j++) {
            int pg = p0 + tx*4 + j;
            if (pg < NFREQ) {
                int fp = f*NFREQ + pg;
                g_V[(size_t)l*FPS + fp]        = cr[i][j];
                g_V[(size_t)(KT + l)*FPS + fp] = ci[i][j];
            }
        }
    }
}

// ---------------- stage 2: Re(y) = [Vre;Vim]^T * [Ere;-Eim], fused power+sum ----------------
__global__ void __launch_bounds__(256, 2)
k_s2() {
    int q0 = blockIdx.x * 64;
    int m0 = blockIdx.y * 128;
    int tid = threadIdx.x;
    int tx = tid & 15, ty = tid >> 4;

    __shared__ float As[16][128];
    __shared__ float Bs[16][64];

    float acc[8][4];
    #pragma unroll
    for (int i=0;i<8;i++)
        #pragma unroll
        for (int j=0;j<4;j++) acc[i][j]=0.f;

    for (int kc = 0; kc < 147; kc++) {
        int kb = kc*16;
        #pragma unroll
        for (int e = 0; e < 8; e++) {
            int idx = e*256 + tid;
            int kk = idx >> 7, c = idx & 127;
            int kg = kb + kk;
            As[kk][c] = (kg < K2) ? g_V[(size_t)kg*FPS + m0 + c] : 0.f;
        }
        #pragma unroll
        for (int e = 0; e < 4; e++) {
            int idx = e*256 + tid;
            int kk = idx >> 6, qq = idx & 63;
            int kg = kb + kk, q = q0 + qq;
            Bs[kk][qq] = (kg < K2 && q < NTIME) ? g_E2[kg*NTIME + q] : 0.f;
        }
        __syncthreads();
        #pragma unroll
        for (int kk = 0; kk < 16; kk++) {
            float a[8], b[4];
            #pragma unroll
            for (int i=0;i<8;i++) a[i] = As[kk][ty*8+i];
            #pragma unroll
            for (int j=0;j<4;j++) b[j] = Bs[kk][tx*4+j];
            #pragma unroll
            for (int i=0;i<8;i++)
                #pragma unroll
                for (int j=0;j<4;j++) acc[i][j] += a[i]*b[j];
        }
        __syncthreads();
    }
    // fused epilogue: clamp(power) partial sums per row
    float rs[8];
    #pragma unroll
    for (int i=0;i<8;i++) rs[i]=0.f;
    #pragma unroll
    for (int i=0;i<8;i++) {
        int fp = m0 + ty*8 + i;
        #pragma unroll
        for (int j=0;j<4;j++) {
            int q = q0 + tx*4 + j;
            if (fp < FP && q < NTIME) {
                float v = acc[i][j];
                rs[i] += fmaxf(v*v, 1e-8f);
            }
        }
    }
    #pragma unroll
    for (int i=0;i<8;i++) {
        float v = rs[i];
        #pragma unroll
        for (int o = 8; o > 0; o >>= 1) v += __shfl_down_sync(0xffffffffu, v, o, 16);
        if (tx == 0)
            g_Part[(blockIdx.y*NT2 + blockIdx.x)*128 + ty*8 + i] = v;
    }
}

// ---------------- finalize: deterministic per-filter mean ----------------
__global__ void k_fin(float* __restrict__ out) {
    int f = threadIdx.x;
    if (f >= NFILT) return;
    float s = 0.f;
    for (int p = 0; p < NFREQ; p++) {
        int fp = f*NFREQ + p;
        int mt = fp >> 7, r = fp & 127;
        for (int nt = 0; nt < NT2; nt++)
            s += g_Part[(mt*NT2 + nt)*128 + r];
    }
    out[f] = s * (1.0f / (float)(NFREQ*NTIME));
}

// ---------------- launch ----------------
extern "C" void kernel_launch(void* const* d_in, const int* in_sizes, int n_in,
                              void* d_out, int out_size) {
    (void)in_sizes; (void)n_in; (void)out_size;
    const float* x   = (const float*)d_in[0];
    const float* Hre = (const float*)d_in[1];
    const float* Him = (const float*)d_in[2];
    float* out = (float*)d_out;

    k_tw<<<5, 256>>>();
    k_D <<<(KF*NFREQ + 255)/256, 256>>>();
    k_E2<<<(K2*NTIME + 255)/256, 256>>>();
    k_P <<<dim3(5, NFREQ), 256>>>(x);
    k_X <<<dim3(5, KF),    256>>>();
    k_s1<<<dim3(4, KT),    256>>>(Hre, Him);
    k_s2<<<dim3(NT2, MT1), 256>>>();
    k_fin<<<1, 128>>>(out);
}

// round 2
// speedup vs baseline: 1.4256x; 1.4256x over previous
#include <cuda_runtime.h>
#include <math.h>

// Problem dims
#define NFREQ 211
#define NTIME 390
#define KF    422          // padded freq
#define KT    1170         // padded time
#define NFILT 119
#define PP    212          // padded p stride per filter (mult of 4)
#define MDIM  (NFILT*PP)   // 25228
#define MPAD  25344        // 99*256
#define NMT   99           // m-tiles of 256
#define NQT   7            // q-tiles of 64
#define KFOLD 1170         // folded spectral rows for stage-2

// ---------------- device scratch (static, zero-initialized) ----------------
__device__ float2 g_twP[KT];                         // (cos, -sin) 2pi j/KT
__device__ float  g_t4c[KF], g_t4s[KF];
__device__ __align__(16) float2 g_D1[(size_t)KF*NFREQ];  // (dre, dim)  = e^{+2pi i kp/KF}/KF
__device__ __align__(16) float2 g_D2[(size_t)KF*NFREQ];  // (-dim, dre)
__device__ float  g_E2f[(size_t)KFOLD*NTIME];        // folded inverse-time basis (incl /KT)
__device__ float2 g_P[(size_t)NFREQ*KT];
__device__ float2 g_X[(size_t)KF*KT];
__device__ __align__(16) float g_Vre[(size_t)KT*MPAD];
__device__ __align__(16) float g_Vim[(size_t)KT*MPAD];
__device__ __align__(16) float g_Vf [(size_t)KFOLD*MPAD];
__device__ float  g_Part[NMT*NQT*256];

// ---------------- packed f32x2 FMA ----------------
__device__ __forceinline__ void ffma2(float2 &c, float2 a, float2 b) {
    unsigned long long uc = *reinterpret_cast<unsigned long long*>(&c);
    unsigned long long ua = *reinterpret_cast<unsigned long long*>(&a);
    unsigned long long ub = *reinterpret_cast<unsigned long long*>(&b);
    asm("fma.rn.f32x2 %0, %1, %2, %0;" : "+l"(uc) : "l"(ua), "l"(ub));
    c = *reinterpret_cast<float2*>(&uc);
}

// ---------------- builders ----------------
__global__ void k_tw() {
    int i = blockIdx.x*256 + threadIdx.x;
    if (i < KT) { double s,c; sincospi(2.0*i/KT, &s, &c); g_twP[i] = make_float2((float)c, (float)(-s)); }
    if (i < KF) { double s,c; sincospi(2.0*i/KF, &s, &c); g_t4c[i]=(float)c; g_t4s[i]=(float)s; }
}
__global__ void k_D() {
    int i = blockIdx.x*256 + threadIdx.x;
    if (i >= KF*NFREQ) return;
    int k = i / NFREQ, p = i % NFREQ;
    int r = (k*p) % KF;
    double s,c; sincospi(2.0*r/KF, &s, &c);
    float dre = (float)(c/KF), dim = (float)(s/KF);
    g_D1[i] = make_float2(dre, dim);
    g_D2[i] = make_float2(-dim, dre);
}
__global__ void k_E2f() {
    int i = blockIdx.x*256 + threadIdx.x;
    if (i >= KFOLD*NTIME) return;
    int kap = i / NTIME, q = i % NTIME;
    float val;
    const float inv = 1.0f/(float)KT;
    if (kap == 0)      val = inv;
    else if (kap == 1) val = (q & 1) ? -inv : inv;     // l=585: cos(pi q)
    else if (kap < 586) {
        int l = kap - 1;                                // cos row, l in [1,584]
        int r = (l*q) % KT;
        double s,c; sincospi(2.0*r/KT, &s, &c);
        val = (float)c * inv;
    } else {
        int l = kap - 585;                              // -sin row, l in [1,584]
        int r = (l*q) % KT;
        double s,c; sincospi(2.0*r/KT, &s, &c);
        val = (float)(-s) * inv;
    }
    g_E2f[i] = val;
}

// ---------------- stage 0: X = fft2(pad(100*x)) -----------------
__global__ void k_P(const float* __restrict__ x) {
    __shared__ float2 tw[KT];
    __shared__ float  xs[NTIME];
    int tid = threadIdx.x;
    for (int i = tid; i < KT; i += 256) tw[i] = g_twP[i];
    int u = blockIdx.y;
    for (int i = tid; i < NTIME; i += 256) xs[i] = x[u*NTIME + i] * 100.0f;
    __syncthreads();
    int l = blockIdx.x*256 + tid;
    if (l >= KT) return;
    float2 acc = make_float2(0.f, 0.f);
    int j = 0;
    for (int v = 0; v < NTIME; v++) {
        float xv = xs[v];
        float2 x2 = make_float2(xv, xv);
        ffma2(acc, x2, tw[j]);
        j += l; if (j >= KT) j -= KT;
    }
    g_P[(size_t)u*KT + l] = acc;
}
__global__ void k_X() {
    __shared__ float sc[KF], ss[KF];
    int tid = threadIdx.x;
    for (int i = tid; i < KF; i += 256) { sc[i]=g_t4c[i]; ss[i]=g_t4s[i]; }
    __syncthreads();
    int l = blockIdx.x*256 + tid;
    int k = blockIdx.y;
    if (l >= KT) return;
    float2 acc = make_float2(0.f, 0.f);
    int j = 0;
    for (int u = 0; u < NFREQ; u++) {
        float2 P = g_P[(size_t)u*KT + l];
        float c = sc[j], s = ss[j];
        float2 c2 = make_float2(c, c), s2 = make_float2(s, s);
        float2 Pw = make_float2(P.y, -P.x);
        ffma2(acc, c2, P);
        ffma2(acc, s2, Pw);
        j += k; if (j >= KF) j -= KF;
    }
    g_X[(size_t)k*KT + l] = acc;
}

// ---------------- stage 1: per f, V[p,l] = sum_k D[p,k] * (H[f,k,l]*X[k,l]) ----------------
// CTA: f = blockIdx.z, l-tile 128 rows (i over ty), p-tile 64 cols (j over tx).
__global__ void __launch_bounds__(256, 2)
k_s1(const float* __restrict__ Hre, const float* __restrict__ Him) {
    int f  = blockIdx.z;
    int l0 = blockIdx.y * 128;
    int p0 = blockIdx.x * 64;
    int tid = threadIdx.x;
    int tx = tid & 15, ty = tid >> 4;

    __shared__ __align__(16) float2 Ws[16][128];
    __shared__ __align__(16) float2 Ds1[16][64];
    __shared__ __align__(16) float2 Ds2[16][64];

    float2 c[8][4];
    #pragma unroll
    for (int i=0;i<8;i++)
        #pragma unroll
        for (int j=0;j<4;j++) c[i][j] = make_float2(0.f, 0.f);

    int kk_l   = tid >> 4;
    int lgrp   = (tid & 15) * 8;
    int pgrp   = (tid & 15) * 4;
    const size_t hbase = (size_t)f * KF * KT;

    for (int kc = 0; kc < 27; kc++) {
        int kg = kc*16 + kk_l;
        bool kok = (kg < KF);
        // W loader: W[k,l] = H * X   (coalesced along l)
        #pragma unroll
        for (int e = 0; e < 8; e++) {
            int lg = l0 + lgrp + e;
            float2 w = make_float2(0.f, 0.f);
            if (kok && lg < KT) {
                float2 X  = g_X[(size_t)kg*KT + lg];
                size_t ho = hbase + (size_t)kg*KT + lg;
                float hr = __ldg(&Hre[ho]);
                float hi = __ldg(&Him[ho]);
                w.x = hr*X.x - hi*X.y;
                w.y = hr*X.y + hi*X.x;
            }
            Ws[kk_l][lgrp + e] = w;
        }
        // D loader
        #pragma unroll
        for (int e = 0; e < 4; e++) {
            int pg = p0 + pgrp + e;
            float2 d1 = make_float2(0.f,0.f), d2 = make_float2(0.f,0.f);
            if (kok && pg < NFREQ) {
                d1 = g_D1[(size_t)kg*NFREQ + pg];
                d2 = g_D2[(size_t)kg*NFREQ + pg];
            }
            Ds1[kk_l][pgrp+e] = d1;
            Ds2[kk_l][pgrp+e] = d2;
        }
        __syncthreads();
        #pragma unroll
        for (int kk = 0; kk < 16; kk++) {
            float4 t0 = *(const float4*)&Ds1[kk][tx*4];
            float4 t1 = *(const float4*)&Ds1[kk][tx*4+2];
            float4 u0 = *(const float4*)&Ds2[kk][tx*4];
            float4 u1 = *(const float4*)&Ds2[kk][tx*4+2];
            float2 d1[4] = { {t0.x,t0.y},{t0.z,t0.w},{t1.x,t1.y},{t1.z,t1.w} };
            float2 d2[4] = { {u0.x,u0.y},{u0.z,u0.w},{u1.x,u1.y},{u1.z,u1.w} };
            #pragma unroll
            for (int i = 0; i < 8; i++) {
                float2 w = Ws[kk][ty*8+i];
                float2 wr = make_float2(w.x, w.x);
                float2 wi = make_float2(w.y, w.y);
                #pragma unroll
                for (int j = 0; j < 4; j++) {
                    ffma2(c[i][j], wr, d1[j]);
                    ffma2(c[i][j], wi, d2[j]);
                }
            }
        }
        __syncthreads();
    }
    // epilogue: coalesced float4 writes, layout V[l][m], m = f*PP + p
    int mbase = f*PP + p0 + tx*4;
    bool pok = (p0 + tx*4) <= 208;   // includes pad col p=211 (zeros)
    #pragma unroll
    for (int i = 0; i < 8; i++) {
        int lg = l0 + ty*8 + i;
        if (lg < KT && pok) {
            float4 re = make_float4(c[i][0].x, c[i][1].x, c[i][2].x, c[i][3].x);
            float4 im = make_float4(c[i][0].y, c[i][1].y, c[i][2].y, c[i][3].y);
            *(float4*)&g_Vre[(size_t)lg*MPAD + mbase] = re;
            *(float4*)&g_Vim[(size_t)lg*MPAD + mbase] = im;
        }
    }
}

// ---------------- fold: halve stage-2 K via l <-> KT-l symmetry ----------------
__global__ void k_fold() {
    int kap = blockIdx.x;
    int m = blockIdx.y*256 + threadIdx.x;      // < MPAD exactly
    float v;
    if (kap == 0)        v = g_Vre[m];
    else if (kap == 1)   v = g_Vre[(size_t)585*MPAD + m];
    else if (kap < 586) { int l = kap - 1;   v = g_Vre[(size_t)l*MPAD+m] + g_Vre[(size_t)(KT-l)*MPAD+m]; }
    else                { int l = kap - 585; v = g_Vim[(size_t)l*MPAD+m] - g_Vim[(size_t)(KT-l)*MPAD+m]; }
    g_Vf[(size_t)kap*MPAD + m] = v;
}

// ---------------- stage 2: Re(y) = Vf^T * E2f, fused power+sum ----------------
// CTA: 256 m rows (i over ty=32) x 64 q cols (8 q per thread as 4 float2, tx=8)
__global__ void __launch_bounds__(256, 2)
k_s2() {
    int q0 = blockIdx.x * 64;
    int m0 = blockIdx.y * 256;
    int tid = threadIdx.x;
    int tx = tid & 7, ty = tid >> 3;

    __shared__ float As[16][256];
    __shared__ __align__(16) float Bs[16][64];

    float2 acc[8][4];
    #pragma unroll
    for (int i=0;i<8;i++)
        #pragma unroll
        for (int j=0;j<4;j++) acc[i][j] = make_float2(0.f,0.f);

    for (int kc = 0; kc < 74; kc++) {
        int kb = kc*16;
        #pragma unroll
        for (int e = 0; e < 16; e++) {
            int idx = e*256 + tid;
            int kk = idx >> 8, cc = idx & 255;
            int kg = kb + kk;
            As[kk][cc] = (kg < KFOLD) ? g_Vf[(size_t)kg*MPAD + m0 + cc] : 0.f;
        }
        #pragma unroll
        for (int e = 0; e < 4; e++) {
            int idx = e*256 + tid;
            int kk = idx >> 6, qq = idx & 63;
            int kg = kb + kk, q = q0 + qq;
            Bs[kk][qq] = (kg < KFOLD && q < NTIME) ? g_E2f[(size_t)kg*NTIME + q] : 0.f;
        }
        __syncthreads();
        #pragma unroll
        for (int kk = 0; kk < 16; kk++) {
            float4 b01 = *(const float4*)&Bs[kk][tx*8];
            float4 b23 = *(const float4*)&Bs[kk][tx*8+4];
            float2 b[4] = { {b01.x,b01.y},{b01.z,b01.w},{b23.x,b23.y},{b23.z,b23.w} };
            #pragma unroll
            for (int i = 0; i < 8; i++) {
                float a = As[kk][ty*8+i];
                float2 a2 = make_float2(a, a);
                #pragma unroll
                for (int j = 0; j < 4; j++) ffma2(acc[i][j], a2, b[j]);
            }
        }
        __syncthreads();
    }
    // fused epilogue: clamp(power) partial sums, deterministic
    #pragma unroll
    for (int i = 0; i < 8; i++) {
        int m = m0 + ty*8 + i;
        int ff = m / PP;
        int p  = m - ff*PP;
        bool mok = (ff < NFILT) && (p < NFREQ);
        float s = 0.f;
        #pragma unroll
        for (int j = 0; j < 4; j++) {
            int q = q0 + tx*8 + 2*j;
            float vx = acc[i][j].x, vy = acc[i][j].y;
            if (mok && q   < NTIME) s += fmaxf(vx*vx, 1e-8f);
            if (mok && q+1 < NTIME) s += fmaxf(vy*vy, 1e-8f);
        }
        s += __shfl_down_sync(0xffffffffu, s, 4, 8);
        s += __shfl_down_sync(0xffffffffu, s, 2, 8);
        s += __shfl_down_sync(0xffffffffu, s, 1, 8);
        if (tx == 0)
            g_Part[(blockIdx.y*NQT + blockIdx.x)*256 + ty*8 + i] = s;
    }
}

// ---------------- finalize: deterministic per-filter mean ----------------
__global__ void k_fin(float* __restrict__ out) {
    int f = threadIdx.x;
    if (f >= NFILT) return;
    float s = 0.f;
    for (int p = 0; p < NFREQ; p++) {
        int m = f*PP + p;
        int mt = m >> 8, r = m & 255;
        for (int nt = 0; nt < NQT; nt++)
            s += g_Part[(mt*NQT + nt)*256 + r];
    }
    out[f] = s * (1.0f / (float)(NFREQ*NTIME));
}

// ---------------- launch ----------------
extern "C" void kernel_launch(void* const* d_in, const int* in_sizes, int n_in,
                              void* d_out, int out_size) {
    (void)in_sizes; (void)n_in; (void)out_size;
    const float* x   = (const float*)d_in[0];
    const float* Hre = (const float*)d_in[1];
    const float* Him = (const float*)d_in[2];
    float* out = (float*)d_out;

    k_tw  <<<5, 256>>>();
    k_D   <<<(KF*NFREQ + 255)/256, 256>>>();
    k_E2f <<<(KFOLD*NTIME + 255)/256, 256>>>();
    k_P   <<<dim3(5, NFREQ), 256>>>(x);
    k_X   <<<dim3(5, KF),    256>>>();
    k_s1  <<<dim3(4, 10, NFILT), 256>>>(Hre, Him);
    k_fold<<<dim3(KFOLD, NMT), 256>>>();
    k_s2  <<<dim3(NQT, NMT), 256>>>();
    k_fin <<<1, 128>>>(out);
}

// round 3
// speedup vs baseline: 1.9539x; 1.3705x over previous
#include <cuda_runtime.h>
#include <math.h>

// Problem dims
#define NFREQ 211
#define NTIME 390
#define KF    422          // padded freq
#define KT    1170         // padded time
#define NFILT 119
#define PP    212          // padded p stride per filter
#define MPAD  25344        // 99*256 (padded m = f*PP+p dimension)
#define NMT   99           // m-tiles of 256
#define NQT   7            // q-tiles of 64
#define KFOLD 1170         // folded time-spectral rows for stage-2
#define KC    224          // folded freq-spectral rows for stage-1 (14 chunks of 16)
#define NQPAD 448          // padded q stride for E2f

// ---------------- device scratch (static, zero-initialized) ----------------
__device__ float2 g_twP[KT];                         // (cos, -sin) 2pi j/KT
__device__ float  g_t4c[KF], g_t4s[KF];
__device__ __align__(16) float2 g_Cf[(size_t)KC*PP]; // folded D coeffs (c, s)
__device__ float  g_E2f[(size_t)KFOLD*NQPAD];        // folded inverse-time basis (incl /KT)
__device__ float2 g_P[(size_t)NFREQ*KT];
__device__ float2 g_X[(size_t)KF*KT];
__device__ __align__(16) float g_Vre[(size_t)KT*MPAD];
__device__ __align__(16) float g_Vim[(size_t)KT*MPAD];
__device__ __align__(16) float g_Vf [(size_t)KFOLD*MPAD];
__device__ float  g_Part[NMT*NQT*256];

// ---------------- packed f32x2 FMA ----------------
__device__ __forceinline__ void ffma2(float2 &c, float2 a, float2 b) {
    unsigned long long uc = *reinterpret_cast<unsigned long long*>(&c);
    unsigned long long ua = *reinterpret_cast<unsigned long long*>(&a);
    unsigned long long ub = *reinterpret_cast<unsigned long long*>(&b);
    asm("fma.rn.f32x2 %0, %1, %2, %0;" : "+l"(uc) : "l"(ua), "l"(ub));
    c = *reinterpret_cast<float2*>(&uc);
}

// ---------------- builders ----------------
__global__ void k_tw() {
    int i = blockIdx.x*256 + threadIdx.x;
    if (i < KT) { double s,c; sincospi(2.0*i/KT, &s, &c); g_twP[i] = make_float2((float)c, (float)(-s)); }
    if (i < KF) { double s,c; sincospi(2.0*i/KF, &s, &c); g_t4c[i]=(float)c; g_t4s[i]=(float)s; }
}
// folded D: V[p] = sum_{kap=0..211} c*S + s*(iT)
__global__ void k_Cf() {
    int i = blockIdx.x*256 + threadIdx.x;
    if (i >= KC*PP) return;
    int kap = i / PP, p = i % PP;
    float cv = 0.f, sv = 0.f;
    const double inv = 1.0/(double)KF;
    if (kap == 0)        { cv = (float)inv; }
    else if (kap < 211)  {
        int r = (kap*p) % KF;
        double s,c; sincospi(2.0*r/KF, &s, &c);
        cv = (float)(c*inv); sv = (float)(s*inv);
    }
    else if (kap == 211) { cv = (p & 1) ? (float)(-inv) : (float)inv; }
    g_Cf[i] = make_float2(cv, sv);
}
__global__ void k_E2f() {
    int i = blockIdx.x*256 + threadIdx.x;
    if (i >= KFOLD*NQPAD) return;
    int kap = i / NQPAD, q = i % NQPAD;
    float val = 0.f;
    const float inv = 1.0f/(float)KT;
    if (q < NTIME) {
        if (kap == 0)      val = inv;
        else if (kap == 1) val = (q & 1) ? -inv : inv;     // l=585: cos(pi q)
        else if (kap < 586) {
            int l = kap - 1;
            int r = (l*q) % KT;
            double s,c; sincospi(2.0*r/KT, &s, &c);
            val = (float)c * inv;
        } else {
            int l = kap - 585;
            int r = (l*q) % KT;
            double s,c; sincospi(2.0*r/KT, &s, &c);
            val = (float)(-s) * inv;
        }
    }
    g_E2f[i] = val;
}

// ---------------- stage 0: X = fft2(pad(100*x)) -----------------
__global__ void k_P(const float* __restrict__ x) {
    __shared__ float2 tw[KT];
    __shared__ float  xs[NTIME];
    int tid = threadIdx.x;
    for (int i = tid; i < KT; i += 256) tw[i] = g_twP[i];
    int u = blockIdx.y;
    for (int i = tid; i < NTIME; i += 256) xs[i] = x[u*NTIME + i] * 100.0f;
    __syncthreads();
    int l = blockIdx.x*256 + tid;
    if (l >= KT) return;
    float2 acc = make_float2(0.f, 0.f);
    int j = 0;
    for (int v = 0; v < NTIME; v++) {
        float xv = xs[v];
        float2 x2 = make_float2(xv, xv);
        ffma2(acc, x2, tw[j]);
        j += l; if (j >= KT) j -= KT;
    }
    g_P[(size_t)u*KT + l] = acc;
}
__global__ void k_X() {
    __shared__ float sc[KF], ss[KF];
    int tid = threadIdx.x;
    for (int i = tid; i < KF; i += 256) { sc[i]=g_t4c[i]; ss[i]=g_t4s[i]; }
    __syncthreads();
    int l = blockIdx.x*256 + tid;
    int k = blockIdx.y;
    if (l >= KT) return;
    float2 acc = make_float2(0.f, 0.f);
    int j = 0;
    for (int u = 0; u < NFREQ; u++) {
        float2 P = g_P[(size_t)u*KT + l];
        float c = sc[j], s = ss[j];
        float2 c2 = make_float2(c, c), s2 = make_float2(s, s);
        float2 Pw = make_float2(P.y, -P.x);
        ffma2(acc, c2, P);
        ffma2(acc, s2, Pw);
        j += k; if (j >= KF) j -= KF;
    }
    g_X[(size_t)k*KT + l] = acc;
}

// ---------------- stage 1 (k-folded): per f, V[p,l] = sum_kap c*S + s*(iT) ----------------
// CTA: 128 threads (tx 16 -> p, ty 8 -> l). Tile 64 l x 128 p. Thread 8l x 8p complex.
__global__ void __launch_bounds__(128, 2)
k_s1(const float* __restrict__ Hre, const float* __restrict__ Him) {
    int f  = blockIdx.z;
    int l0 = blockIdx.y * 64;
    int p0 = blockIdx.x * 84;          // tiles {0, 84} cover p 0..211 (overlap benign)
    int tid = threadIdx.x;
    int tx = tid & 15, ty = tid >> 4;

    __shared__ __align__(16) float2 Ss[16][64];
    __shared__ __align__(16) float2 Ts[16][64];
    __shared__ __align__(16) float2 Cs[16][128];

    float2 acc[8][8];
    #pragma unroll
    for (int i=0;i<8;i++)
        #pragma unroll
        for (int j=0;j<8;j++) acc[i][j] = make_float2(0.f, 0.f);

    const size_t hb = (size_t)f * KF * KT;

    for (int kc = 0; kc < 14; kc++) {
        int kb = kc*16;
        // A loader: S,T folds (coalesced along l)
        #pragma unroll
        for (int e = 0; e < 8; e++) {
            int idx = e*128 + tid;
            int kcc = idx >> 6, lc = idx & 63;
            int kg = kb + kcc;
            int lg = l0 + lc;
            float2 S = make_float2(0.f,0.f), T = make_float2(0.f,0.f);
            if (kg < 212 && lg < KT) {
                float2 X = g_X[(size_t)kg*KT + lg];
                size_t ho = hb + (size_t)kg*KT + lg;
                float hr = __ldg(&Hre[ho]), hi = __ldg(&Him[ho]);
                float2 Wa = make_float2(hr*X.x - hi*X.y, hr*X.y + hi*X.x);
                if (kg >= 1 && kg < 211) {
                    int km = KF - kg;
                    float2 X2 = g_X[(size_t)km*KT + lg];
                    size_t ho2 = hb + (size_t)km*KT + lg;
                    float hr2 = __ldg(&Hre[ho2]), hi2 = __ldg(&Him[ho2]);
                    float2 Wb = make_float2(hr2*X2.x - hi2*X2.y, hr2*X2.y + hi2*X2.x);
                    S = make_float2(Wa.x + Wb.x, Wa.y + Wb.y);
                    T = make_float2(Wa.x - Wb.x, Wa.y - Wb.y);
                } else {
                    S = Wa;
                }
            }
            Ss[kcc][lc] = S; Ts[kcc][lc] = T;
        }
        // B loader
        #pragma unroll
        for (int e = 0; e < 16; e++) {
            int idx = e*128 + tid;
            int kcc = idx >> 7, pc = idx & 127;
            Cs[kcc][pc] = g_Cf[(size_t)(kb + kcc)*PP + p0 + pc];
        }
        __syncthreads();
        #pragma unroll
        for (int kk = 0; kk < 16; kk++) {
            const float4* sp = reinterpret_cast<const float4*>(&Ss[kk][ty*8]);
            const float4* tp = reinterpret_cast<const float4*>(&Ts[kk][ty*8]);
            float4 s0=sp[0], s1=sp[1], s2=sp[2], s3=sp[3];
            float4 t0=tp[0], t1=tp[1], t2=tp[2], t3=tp[3];
            float2 S[8] = {{s0.x,s0.y},{s0.z,s0.w},{s1.x,s1.y},{s1.z,s1.w},
                           {s2.x,s2.y},{s2.z,s2.w},{s3.x,s3.y},{s3.z,s3.w}};
            float2 iT[8] = {{-t0.y,t0.x},{-t0.w,t0.z},{-t1.y,t1.x},{-t1.w,t1.z},
                            {-t2.y,t2.x},{-t2.w,t2.z},{-t3.y,t3.x},{-t3.w,t3.z}};
            float2 cc[8], ssb[8];
            #pragma unroll
            for (int j = 0; j < 8; j++) {
                float2 C = Cs[kk][j*16 + tx];      // conflict-free LDS.64
                cc[j]  = make_float2(C.x, C.x);
                ssb[j] = make_float2(C.y, C.y);
            }
            #pragma unroll
            for (int i = 0; i < 8; i++) {
                float2 Si = S[i], iTi = iT[i];
                #pragma unroll
                for (int j = 0; j < 8; j++) {
                    ffma2(acc[i][j], cc[j],  Si);
                    ffma2(acc[i][j], ssb[j], iTi);
                }
            }
        }
        __syncthreads();
    }
    // epilogue: V[l][m], m = f*PP + p0 + j*16 + tx
    #pragma unroll
    for (int i = 0; i < 8; i++) {
        int lg = l0 + ty*8 + i;
        if (lg < KT) {
            size_t base = (size_t)lg*MPAD + f*PP + p0;
            #pragma unroll
            for (int j = 0; j < 8; j++) {
                int pc = j*16 + tx;
                g_Vre[base + pc] = acc[i][j].x;
                g_Vim[base + pc] = acc[i][j].y;
            }
        }
    }
}

// ---------------- fold: halve stage-2 K via l <-> KT-l symmetry ----------------
__global__ void k_fold() {
    int kap = blockIdx.x;
    int m = blockIdx.y*256 + threadIdx.x;
    float v;
    if (kap == 0)        v = g_Vre[m];
    else if (kap == 1)   v = g_Vre[(size_t)585*MPAD + m];
    else if (kap < 586) { int l = kap - 1;   v = g_Vre[(size_t)l*MPAD+m] + g_Vre[(size_t)(KT-l)*MPAD+m]; }
    else                { int l = kap - 585; v = g_Vim[(size_t)l*MPAD+m] - g_Vim[(size_t)(KT-l)*MPAD+m]; }
    g_Vf[(size_t)kap*MPAD + m] = v;
}

// ---------------- stage 2: Re(y) = Vf^T * E2f, fused power+sum ----------------
// CTA: 128 threads (tx 8 -> q, ty 16 -> m). Tile 256 m x 64 q. Thread 16m x 8q.
__global__ void __launch_bounds__(128, 2)
k_s2() {
    int q0 = blockIdx.x * 64;
    int m0 = blockIdx.y * 256;
    int tid = threadIdx.x;
    int tx = tid & 7, ty = tid >> 3;

    __shared__ __align__(16) float As[16][256];
    __shared__ __align__(16) float Bs[16][64];

    float2 acc[16][4];
    #pragma unroll
    for (int i=0;i<16;i++)
        #pragma unroll
        for (int j=0;j<4;j++) acc[i][j] = make_float2(0.f,0.f);

    const float4 fz = make_float4(0.f,0.f,0.f,0.f);
    for (int kc = 0; kc < 74; kc++) {
        int kb = kc*16;
        #pragma unroll
        for (int e = 0; e < 8; e++) {
            int fi = e*512 + tid*4;
            int kk = fi >> 8, c = fi & 255;
            int kg = kb + kk;
            float4 v = (kg < KFOLD) ? *(const float4*)&g_Vf[(size_t)kg*MPAD + m0 + c] : fz;
            *(float4*)&As[kk][c] = v;
        }
        #pragma unroll
        for (int e = 0; e < 2; e++) {
            int fi = e*512 + tid*4;
            int kk = fi >> 6, c = fi & 63;
            int kg = kb + kk;
            float4 v = (kg < KFOLD) ? *(const float4*)&g_E2f[(size_t)kg*NQPAD + q0 + c] : fz;
            *(float4*)&Bs[kk][c] = v;
        }
        __syncthreads();
        #pragma unroll
        for (int kk = 0; kk < 16; kk++) {
            const float4* ap = reinterpret_cast<const float4*>(&As[kk][ty*16]);
            float4 a0=ap[0], a1=ap[1], a2=ap[2], a3=ap[3];
            float a[16] = {a0.x,a0.y,a0.z,a0.w, a1.x,a1.y,a1.z,a1.w,
                           a2.x,a2.y,a2.z,a2.w, a3.x,a3.y,a3.z,a3.w};
            float2 b[4];
            #pragma unroll
            for (int j = 0; j < 4; j++)
                b[j] = reinterpret_cast<const float2*>(&Bs[kk][0])[j*8 + tx];
            #pragma unroll
            for (int i = 0; i < 16; i++) {
                float2 ai = make_float2(a[i], a[i]);
                #pragma unroll
                for (int j = 0; j < 4; j++) ffma2(acc[i][j], ai, b[j]);
            }
        }
        __syncthreads();
    }
    // fused epilogue: clamp(power) partial sums, deterministic
    #pragma unroll
    for (int i = 0; i < 16; i++) {
        int m = m0 + ty*16 + i;
        int ff = m / PP;
        int p  = m - ff*PP;
        bool mok = (ff < NFILT) && (p < NFREQ);
        float s = 0.f;
        #pragma unroll
        for (int j = 0; j < 4; j++) {
            int q = q0 + (j*8 + tx)*2;
            float vx = acc[i][j].x, vy = acc[i][j].y;
            if (mok && q   < NTIME) s += fmaxf(vx*vx, 1e-8f);
            if (mok && q+1 < NTIME) s += fmaxf(vy*vy, 1e-8f);
        }
        s += __shfl_down_sync(0xffffffffu, s, 4, 8);
        s += __shfl_down_sync(0xffffffffu, s, 2, 8);
        s += __shfl_down_sync(0xffffffffu, s, 1, 8);
        if (tx == 0)
            g_Part[(blockIdx.y*NQT + blockIdx.x)*256 + ty*16 + i] = s;
    }
}

// ---------------- finalize: deterministic per-filter mean ----------------
__global__ void k_fin(float* __restrict__ out) {
    int f = threadIdx.x;
    if (f >= NFILT) return;
    float s = 0.f;
    for (int p = 0; p < NFREQ; p++) {
        int m = f*PP + p;
        int mt = m >> 8, r = m & 255;
        for (int nt = 0; nt < NQT; nt++)
            s += g_Part[(mt*NQT + nt)*256 + r];
    }
    out[f] = s * (1.0f / (float)(NFREQ*NTIME));
}

// ---------------- launch ----------------
extern "C" void kernel_launch(void* const* d_in, const int* in_sizes, int n_in,
                              void* d_out, int out_size) {
    (void)in_sizes; (void)n_in; (void)out_size;
    const float* x   = (const float*)d_in[0];
    const float* Hre = (const float*)d_in[1];
    const float* Him = (const float*)d_in[2];
    float* out = (float*)d_out;

    k_tw  <<<5, 256>>>();
    k_Cf  <<<(KC*PP + 255)/256, 256>>>();
    k_E2f <<<(KFOLD*NQPAD + 255)/256, 256>>>();
    k_P   <<<dim3(5, NFREQ), 256>>>(x);
    k_X   <<<dim3(5, KF),    256>>>();
    k_s1  <<<dim3(2, 19, NFILT), 128>>>(Hre, Him);
    k_fold<<<dim3(KFOLD, NMT), 256>>>();
    k_s2  <<<dim3(NQT, NMT), 128>>>();
    k_fin <<<1, 128>>>(out);
}

// round 5
// speedup vs baseline: 2.9315x; 1.5003x over previous
#include <cuda_runtime.h>
#include <cuda_bf16.h>
#include <mma.h>
#include <math.h>
#include <stdint.h>

using namespace nvcuda;

// Problem dims
#define NFREQ 211
#define NTIME 390
#define KF    422
#define KT    1170
#define NFILT 119
#define PP    224            // padded p stride per filter (GEMM N)
#define MPAD  26880          // 105*256
#define NMT   105            // m-tiles of 256 (stage 2)
#define NQT   7              // q-tiles of 64
#define KFOLD 1170
#define NQPAD 448
#define KP    448            // stage-1 K' (S/iT interleaved, kap padded to 224)
#define NCHUNK 14            // K' chunks of 32 (16 kap each)
#define LTILE 19             // l tiles of 64 (1216 >= 1170)

// ---------------- device scratch ----------------
__device__ float2 g_twP[KT];
__device__ float  g_t4c[KF], g_t4s[KF];
__device__ __align__(16) __nv_bfloat16 g_Bhi[(size_t)PP*KP];
__device__ __align__(16) __nv_bfloat16 g_Blo[(size_t)PP*KP];
__device__ float  g_E2f[(size_t)KFOLD*NQPAD];
__device__ float2 g_P[(size_t)NFREQ*KT];
__device__ float2 g_X[(size_t)KF*KT];
__device__ __align__(16) float g_Vre[(size_t)KT*MPAD];
__device__ __align__(16) float g_Vim[(size_t)KT*MPAD];
__device__ __align__(16) float g_Vf [(size_t)KFOLD*MPAD];
__device__ float  g_Part[NMT*NQT*256];

// ---------------- helpers ----------------
__device__ __forceinline__ void ffma2(float2 &c, float2 a, float2 b) {
    unsigned long long uc = *reinterpret_cast<unsigned long long*>(&c);
    unsigned long long ua = *reinterpret_cast<unsigned long long*>(&a);
    unsigned long long ub = *reinterpret_cast<unsigned long long*>(&b);
    asm("fma.rn.f32x2 %0, %1, %2, %0;" : "+l"(uc) : "l"(ua), "l"(ub));
    c = *reinterpret_cast<float2*>(&uc);
}

// ---------------- builders ----------------
__global__ void k_tw() {
    int i = blockIdx.x*256 + threadIdx.x;
    if (i < KT) { double s,c; sincospi(2.0*i/KT, &s, &c); g_twP[i] = make_float2((float)c, (float)(-s)); }
    if (i < KF) { double s,c; sincospi(2.0*i/KF, &s, &c); g_t4c[i]=(float)c; g_t4s[i]=(float)s; }
}
__global__ void k_Bsplit() {
    int i = blockIdx.x*256 + threadIdx.x;
    if (i >= PP*KP) return;
    int p = i / KP, k = i % KP;
    int kap = k >> 1; int iss = k & 1;
    double v = 0.0;
    const double inv = 1.0/(double)KF;
    if (p < NFREQ && kap <= 211) {
        if (kap == 0)        v = iss ? 0.0 : inv;
        else if (kap == 211) v = iss ? 0.0 : ((p & 1) ? -inv : inv);
        else {
            int r = (kap*p) % KF;
            double s,c; sincospi(2.0*r/KF, &s, &c);
            v = (iss ? s : c) * inv;
        }
    }
    float vf = (float)v;
    __nv_bfloat16 h = __float2bfloat16(vf);
    float lo = vf - __bfloat162float(h);
    g_Bhi[i] = h;
    g_Blo[i] = __float2bfloat16(lo);
}
__global__ void k_E2f() {
    int i = blockIdx.x*256 + threadIdx.x;
    if (i >= KFOLD*NQPAD) return;
    int kap = i / NQPAD, q = i % NQPAD;
    float val = 0.f;
    const float inv = 1.0f/(float)KT;
    if (q < NTIME) {
        if (kap == 0)      val = inv;
        else if (kap == 1) val = (q & 1) ? -inv : inv;
        else if (kap < 586) {
            int l = kap - 1;
            int r = (l*q) % KT;
            double s,c; sincospi(2.0*r/KT, &s, &c);
            val = (float)c * inv;
        } else {
            int l = kap - 585;
            int r = (l*q) % KT;
            double s,c; sincospi(2.0*r/KT, &s, &c);
            val = (float)(-s) * inv;
        }
    }
    g_E2f[i] = val;
}

// ---------------- stage 0: X = fft2(pad(100*x)) -----------------
__global__ void k_P(const float* __restrict__ x) {
    __shared__ float2 tw[KT];
    __shared__ float  xs[NTIME];
    int tid = threadIdx.x;
    for (int i = tid; i < KT; i += 256) tw[i] = g_twP[i];
    int u = blockIdx.y;
    for (int i = tid; i < NTIME; i += 256) xs[i] = x[u*NTIME + i] * 100.0f;
    __syncthreads();
    int l = blockIdx.x*256 + tid;
    if (l >= KT) return;
    float2 acc = make_float2(0.f, 0.f);
    int j = 0;
    for (int v = 0; v < NTIME; v++) {
        float xv = xs[v];
        float2 x2 = make_float2(xv, xv);
        ffma2(acc, x2, tw[j]);
        j += l; if (j >= KT) j -= KT;
    }
    g_P[(size_t)u*KT + l] = acc;
}
__global__ void k_X() {
    __shared__ float sc[KF], ss[KF];
    int tid = threadIdx.x;
    for (int i = tid; i < KF; i += 256) { sc[i]=g_t4c[i]; ss[i]=g_t4s[i]; }
    __syncthreads();
    int l = blockIdx.x*256 + tid;
    int k = blockIdx.y;
    if (l >= KT) return;
    float2 acc = make_float2(0.f, 0.f);
    int j = 0;
    for (int u = 0; u < NFREQ; u++) {
        float2 P = g_P[(size_t)u*KT + l];
        float c = sc[j], s = ss[j];
        float2 c2 = make_float2(c, c), s2 = make_float2(s, s);
        float2 Pw = make_float2(P.y, -P.x);
        ffma2(acc, c2, P);
        ffma2(acc, s2, Pw);
        j += k; if (j >= KF) j -= KF;
    }
    g_X[(size_t)k*KT + l] = acc;
}

// ---------------- stage 1: wmma bf16 3-pass split GEMM ----------------
// grid (LTILE, NFILT), 256 threads (8 warps, 4M x 2N).
// Tile: M=128 (rows 0-63: Re of l0+r, rows 64-127: Im), N=224 (p), K'=448.
// A built in-kernel (fold of H*X), B prebuilt (c/s DFT coeffs), f32 accum.
#define ASTR 40
#define BSTR 40
#define CSTR 232
#define SM_AHI 0
#define SM_ALO (SM_AHI + 128*ASTR*2)            // 10240
#define SM_BHI (SM_ALO + 128*ASTR*2)            // 20480
#define SM_BLO (SM_BHI + PP*BSTR*2)             // 38400
#define SM_CS  (SM_BLO + PP*BSTR*2)             // 56320
#define SM_TOT (SM_CS + 128*CSTR*4)             // 175104

__global__ void __launch_bounds__(256)
k_s1mma(const float* __restrict__ Hre, const float* __restrict__ Him) {
    extern __shared__ char smem[];
    __nv_bfloat16* Ahi = (__nv_bfloat16*)(smem + SM_AHI);
    __nv_bfloat16* Alo = (__nv_bfloat16*)(smem + SM_ALO);
    __nv_bfloat16* Bhi = (__nv_bfloat16*)(smem + SM_BHI);
    __nv_bfloat16* Blo = (__nv_bfloat16*)(smem + SM_BLO);
    float*         Cs  = (float*)(smem + SM_CS);

    int tid = threadIdx.x;
    int f  = blockIdx.y;
    int l0 = blockIdx.x * 64;

    int wid = tid >> 5;
    int wm = wid & 3, wn = wid >> 2;          // 4M x 2N
    int mb = wm * 32, nb = wn * 112;

    wmma::fragment<wmma::accumulator, 16, 16, 16, float> acc[2][7];
    #pragma unroll
    for (int mi = 0; mi < 2; mi++)
        #pragma unroll
        for (int ni = 0; ni < 7; ni++) wmma::fill_fragment(acc[mi][ni], 0.0f);

    int lc = tid & 63;
    int kq = tid >> 6;                        // 0..3
    int lg = l0 + lc;
    bool lok = (lg < KT);
    const size_t hb = (size_t)f * KF * KT;

    for (int ch = 0; ch < NCHUNK; ch++) {
        // ---- build A (fold): 16 kap x 64 l per chunk ----
        #pragma unroll
        for (int j = 0; j < 4; j++) {
            int ka = kq + j*4;                // 0..15
            int kg = ch*16 + ka;
            float Sx=0.f, Sy=0.f, iTx=0.f, iTy=0.f;
            if (lok && kg <= 211) {
                float2 X = g_X[(size_t)kg*KT + lg];
                float hr = Hre[hb + (size_t)kg*KT + lg];
                float hi = Him[hb + (size_t)kg*KT + lg];
                float war = hr*X.x - hi*X.y;
                float wai = hr*X.y + hi*X.x;
                if (kg >= 1 && kg <= 210) {
                    int km = KF - kg;
                    float2 X2 = g_X[(size_t)km*KT + lg];
                    float hr2 = Hre[hb + (size_t)km*KT + lg];
                    float hi2 = Him[hb + (size_t)km*KT + lg];
                    float wbr = hr2*X2.x - hi2*X2.y;
                    float wbi = hr2*X2.y + hi2*X2.x;
                    Sx = war + wbr; Sy = wai + wbi;
                    float Tx = war - wbr, Ty = wai - wbi;
                    iTx = -Ty; iTy = Tx;
                } else { Sx = war; Sy = wai; }
            }
            // rows: lc -> (Sx, iTx); 64+lc -> (Sy, iTy); cols 2ka, 2ka+1
            {
                __nv_bfloat16 h0 = __float2bfloat16(Sx);
                __nv_bfloat16 h1 = __float2bfloat16(iTx);
                float e0 = Sx - __bfloat162float(h0);
                float e1 = iTx - __bfloat162float(h1);
                uint32_t hp = (uint32_t)__bfloat16_as_ushort(h0) | ((uint32_t)__bfloat16_as_ushort(h1) << 16);
                uint32_t lp = (uint32_t)__bfloat16_as_ushort(__float2bfloat16(e0)) |
                              ((uint32_t)__bfloat16_as_ushort(__float2bfloat16(e1)) << 16);
                *(uint32_t*)&Ahi[lc*ASTR + 2*ka] = hp;
                *(uint32_t*)&Alo[lc*ASTR + 2*ka] = lp;
            }
            {
                __nv_bfloat16 h0 = __float2bfloat16(Sy);
                __nv_bfloat16 h1 = __float2bfloat16(iTy);
                float e0 = Sy - __bfloat162float(h0);
                float e1 = iTy - __bfloat162float(h1);
                uint32_t hp = (uint32_t)__bfloat16_as_ushort(h0) | ((uint32_t)__bfloat16_as_ushort(h1) << 16);
                uint32_t lp = (uint32_t)__bfloat16_as_ushort(__float2bfloat16(e0)) |
                              ((uint32_t)__bfloat16_as_ushort(__float2bfloat16(e1)) << 16);
                *(uint32_t*)&Ahi[(64+lc)*ASTR + 2*ka] = hp;
                *(uint32_t*)&Alo[(64+lc)*ASTR + 2*ka] = lp;
            }
        }
        // ---- load B: 224 rows x 32 k' (hi & lo) ----
        #pragma unroll
        for (int i = tid; i < 896; i += 256) {
            int row = i >> 2, seg = i & 3;
            size_t src = (size_t)row*KP + ch*32 + seg*8;
            uint4 vh = *(const uint4*)&g_Bhi[src];
            uint4 vl = *(const uint4*)&g_Blo[src];
            *(uint4*)&Bhi[row*BSTR + seg*8] = vh;
            *(uint4*)&Blo[row*BSTR + seg*8] = vl;
        }
        __syncthreads();

        // ---- MMA: 2 k-steps of 16, 3-pass bf16 split ----
        #pragma unroll
        for (int ks = 0; ks < 2; ks++) {
            wmma::fragment<wmma::matrix_a, 16, 16, 16, __nv_bfloat16, wmma::row_major> ah[2], al[2];
            wmma::fragment<wmma::matrix_b, 16, 16, 16, __nv_bfloat16, wmma::col_major> bh[7], bl[7];
            #pragma unroll
            for (int mi = 0; mi < 2; mi++) {
                wmma::load_matrix_sync(ah[mi], &Ahi[(mb + mi*16)*ASTR + ks*16], ASTR);
                wmma::load_matrix_sync(al[mi], &Alo[(mb + mi*16)*ASTR + ks*16], ASTR);
            }
            #pragma unroll
            for (int ni = 0; ni < 7; ni++) {
                wmma::load_matrix_sync(bh[ni], &Bhi[(nb + ni*16)*BSTR + ks*16], BSTR);
                wmma::load_matrix_sync(bl[ni], &Blo[(nb + ni*16)*BSTR + ks*16], BSTR);
            }
            #pragma unroll
            for (int mi = 0; mi < 2; mi++)
                #pragma unroll
                for (int ni = 0; ni < 7; ni++) {
                    wmma::mma_sync(acc[mi][ni], ah[mi], bh[ni], acc[mi][ni]);
                    wmma::mma_sync(acc[mi][ni], ah[mi], bl[ni], acc[mi][ni]);
                    wmma::mma_sync(acc[mi][ni], al[mi], bh[ni], acc[mi][ni]);
                }
        }
        __syncthreads();
    }

    // ---- epilogue: stage to smem, masked coalesced writes ----
    #pragma unroll
    for (int mi = 0; mi < 2; mi++)
        #pragma unroll
        for (int ni = 0; ni < 7; ni++)
            wmma::store_matrix_sync(&Cs[(mb + mi*16)*CSTR + nb + ni*16], acc[mi][ni],
                                    CSTR, wmma::mem_row_major);
    __syncthreads();

    size_t fb = (size_t)f * PP;
    for (int i = tid; i < 128*56; i += 256) {
        int row = i / 56, c4 = i % 56;
        float4 v = *(float4*)&Cs[row*CSTR + c4*4];
        if (row < 64) {
            int l = l0 + row;
            if (l < KT) *(float4*)&g_Vre[(size_t)l*MPAD + fb + c4*4] = v;
        } else {
            int l = l0 + row - 64;
            if (l < KT) *(float4*)&g_Vim[(size_t)l*MPAD + fb + c4*4] = v;
        }
    }
}

// ---------------- fold: halve stage-2 K via l <-> KT-l symmetry ----------------
__global__ void k_fold() {
    int kap = blockIdx.x;
    int m = blockIdx.y*256 + threadIdx.x;
    float v;
    if (kap == 0)        v = g_Vre[m];
    else if (kap == 1)   v = g_Vre[(size_t)585*MPAD + m];
    else if (kap < 586) { int l = kap - 1;   v = g_Vre[(size_t)l*MPAD+m] + g_Vre[(size_t)(KT-l)*MPAD+m]; }
    else                { int l = kap - 585; v = g_Vim[(size_t)l*MPAD+m] - g_Vim[(size_t)(KT-l)*MPAD+m]; }
    g_Vf[(size_t)kap*MPAD + m] = v;
}

// ---------------- stage 2: Re(y) = Vf^T * E2f, fused power+sum ----------------
__global__ void __launch_bounds__(128, 2)
k_s2() {
    int q0 = blockIdx.x * 64;
    int m0 = blockIdx.y * 256;
    int tid = threadIdx.x;
    int tx = tid & 7, ty = tid >> 3;

    __shared__ __align__(16) float As[16][256];
    __shared__ __align__(16) float Bs[16][64];

    float2 acc[16][4];
    #pragma unroll
    for (int i=0;i<16;i++)
        #pragma unroll
        for (int j=0;j<4;j++) acc[i][j] = make_float2(0.f,0.f);

    const float4 fz = make_float4(0.f,0.f,0.f,0.f);
    for (int kc = 0; kc < 74; kc++) {
        int kb = kc*16;
        #pragma unroll
        for (int e = 0; e < 8; e++) {
            int fi = e*512 + tid*4;
            int kk = fi >> 8, c = fi & 255;
            int kg = kb + kk;
            float4 v = (kg < KFOLD) ? *(const float4*)&g_Vf[(size_t)kg*MPAD + m0 + c] : fz;
            *(float4*)&As[kk][c] = v;
        }
        #pragma unroll
        for (int e = 0; e < 2; e++) {
            int fi = e*512 + tid*4;
            int kk = fi >> 6, c = fi & 63;
            int kg = kb + kk;
            float4 v = (kg < KFOLD) ? *(const float4*)&g_E2f[(size_t)kg*NQPAD + q0 + c] : fz;
            *(float4*)&Bs[kk][c] = v;
        }
        __syncthreads();
        #pragma unroll
        for (int kk = 0; kk < 16; kk++) {
            const float4* ap = reinterpret_cast<const float4*>(&As[kk][ty*16]);
            float4 a0=ap[0], a1=ap[1], a2=ap[2], a3=ap[3];
            float a[16] = {a0.x,a0.y,a0.z,a0.w, a1.x,a1.y,a1.z,a1.w,
                           a2.x,a2.y,a2.z,a2.w, a3.x,a3.y,a3.z,a3.w};
            float2 b[4];
            #pragma unroll
            for (int j = 0; j < 4; j++)
                b[j] = reinterpret_cast<const float2*>(&Bs[kk][0])[j*8 + tx];
            #pragma unroll
            for (int i = 0; i < 16; i++) {
                float2 ai = make_float2(a[i], a[i]);
                #pragma unroll
                for (int j = 0; j < 4; j++) ffma2(acc[i][j], ai, b[j]);
            }
        }
        __syncthreads();
    }
    #pragma unroll
    for (int i = 0; i < 16; i++) {
        int m = m0 + ty*16 + i;
        int ff = m / PP;
        int p  = m - ff*PP;
        bool mok = (ff < NFILT) && (p < NFREQ);
        float s = 0.f;
        #pragma unroll
        for (int j = 0; j < 4; j++) {
            int q = q0 + (j*8 + tx)*2;
            float vx = acc[i][j].x, vy = acc[i][j].y;
            if (mok && q   < NTIME) s += fmaxf(vx*vx, 1e-8f);
            if (mok && q+1 < NTIME) s += fmaxf(vy*vy, 1e-8f);
        }
        s += __shfl_down_sync(0xffffffffu, s, 4, 8);
        s += __shfl_down_sync(0xffffffffu, s, 2, 8);
        s += __shfl_down_sync(0xffffffffu, s, 1, 8);
        if (tx == 0)
            g_Part[(blockIdx.y*NQT + blockIdx.x)*256 + ty*16 + i] = s;
    }
}

// ---------------- finalize ----------------
__global__ void k_fin(float* __restrict__ out) {
    int f = threadIdx.x;
    if (f >= NFILT) return;
    float s = 0.f;
    for (int p = 0; p < NFREQ; p++) {
        int m = f*PP + p;
        int mt = m >> 8, r = m & 255;
        for (int nt = 0; nt < NQT; nt++)
            s += g_Part[(mt*NQT + nt)*256 + r];
    }
    out[f] = s * (1.0f / (float)(NFREQ*NTIME));
}

// ---------------- launch ----------------
extern "C" void kernel_launch(void* const* d_in, const int* in_sizes, int n_in,
                              void* d_out, int out_size) {
    (void)in_sizes; (void)n_in; (void)out_size;
    const float* x   = (const float*)d_in[0];
    const float* Hre = (const float*)d_in[1];
    const float* Him = (const float*)d_in[2];
    float* out = (float*)d_out;

    cudaFuncSetAttribute(k_s1mma, cudaFuncAttributeMaxDynamicSharedMemorySize, SM_TOT);

    k_tw     <<<5, 256>>>();
    k_Bsplit <<<(PP*KP + 255)/256, 256>>>();
    k_E2f    <<<(KFOLD*NQPAD + 255)/256, 256>>>();
    k_P      <<<dim3(5, NFREQ), 256>>>(x);
    k_X      <<<dim3(5, KF),    256>>>();
    k_s1mma  <<<dim3(LTILE, NFILT), 256, SM_TOT>>>(Hre, Him);
    k_fold   <<<dim3(KFOLD, NMT), 256>>>();
    k_s2     <<<dim3(NQT, NMT), 128>>>();
    k_fin    <<<1, 128>>>(out);
}